// round 16
// baseline (speedup 1.0000x reference)
// GroupMLP round 16 — r15 winner (1-pass fp16 MMA) + h stored as fp16.
// Regime shifted to DRAM-bound after r15 halved the MMA stream, so the
// -410MB h-traffic cut (which lost in the issue-bound r14 regime) now binds.
#include <cuda_runtime.h>
#include <cuda_fp16.h>

#define H 8
#define FIN 128
#define HID 128
#define FOUT 64
#define LDA 136          // padded smem stride (elems): 272B rows -> ldmatrix conflict-free
#define NMAX 131072
#define NTMAX (NMAX / 128)
#define NCH 16

// Scratch (static device globals; no runtime allocation)
__device__ __half g_h[(size_t)NMAX * H * HID];        // intermediate h [N,H,HID], fp16
__device__ float g_psum[(size_t)H * NTMAX * HID];     // per-tile column sums
__device__ float g_psumsq[(size_t)H * NTMAX * HID];
__device__ float g_ps2[H * NCH * HID];
__device__ float g_pq2[H * NCH * HID];
__device__ float g_scale[H * HID];
__device__ float g_shift[H * HID];

// Pre-converted fp16 weights, already in [n][k]*LDA smem layout
__device__ __half g_w1h[H * 128 * LDA];
__device__ __half g_w2h[H * 64 * LDA];

// 8-byte packed store of 4 fp16
__device__ __forceinline__ void st_h4(__half *p, __half a, __half b, __half c, __half d) {
    __half2 t0 = __halves2half2(a, b);
    __half2 t1 = __halves2half2(c, d);
    uint2 t;
    t.x = *reinterpret_cast<unsigned *>(&t0);
    t.y = *reinterpret_cast<unsigned *>(&t1);
    *reinterpret_cast<uint2 *>(p) = t;
}

__device__ __forceinline__ void cpasync16(unsigned saddr, const void *gaddr) {
    asm volatile("cp.async.ca.shared.global [%0], [%1], 16;\n" :: "r"(saddr), "l"(gaddr));
}
__device__ __forceinline__ void cpasync_commit() { asm volatile("cp.async.commit_group;\n"); }
__device__ __forceinline__ void cpasync_wait0()  { asm volatile("cp.async.wait_group 0;\n"); }

__device__ __forceinline__ void ldsm4(unsigned &r0, unsigned &r1, unsigned &r2, unsigned &r3,
                                      unsigned addr) {
    asm volatile("ldmatrix.sync.aligned.m8n8.x4.shared.b16 {%0,%1,%2,%3}, [%4];\n"
                 : "=r"(r0), "=r"(r1), "=r"(r2), "=r"(r3) : "r"(addr));
}

__device__ __forceinline__ void mma16816h(float c[4], const unsigned a[4],
                                          unsigned b0, unsigned b1) {
    asm volatile(
        "mma.sync.aligned.m16n8k16.row.col.f32.f16.f16.f32 "
        "{%0,%1,%2,%3}, {%4,%5,%6,%7}, {%8,%9}, {%0,%1,%2,%3};\n"
        : "+f"(c[0]), "+f"(c[1]), "+f"(c[2]), "+f"(c[3])
        : "r"(a[0]), "r"(a[1]), "r"(a[2]), "r"(a[3]), "r"(b0), "r"(b1));
}

// ---------------------------------------------------------------------------
// K0: convert weights to fp16, transposed to [n][k]*LDA layout.
// ---------------------------------------------------------------------------
__global__ void k_prep(const float *__restrict__ w1, const float *__restrict__ w2)
{
    const int hd = blockIdx.x;
    const int tid = threadIdx.x;
    const float *w1h = w1 + (size_t)hd * FIN * HID;
    __half *o1 = g_w1h + (size_t)hd * 128 * LDA;
    for (int i = tid; i < 128 * 128; i += blockDim.x) {
        int n = i & 127, k = i >> 7;
        o1[n * LDA + k] = __float2half_rn(w1h[(size_t)k * HID + n]);
    }
    const float *w2h = w2 + (size_t)hd * HID * FOUT;
    __half *o2 = g_w2h + (size_t)hd * 64 * LDA;
    for (int i = tid; i < 64 * 128; i += blockDim.x) {
        int n = i & 63, k = i >> 6;
        o2[n * LDA + k] = __float2half_rn(w2h[(size_t)k * FOUT + n]);
    }
}

// ---------------------------------------------------------------------------
// K1: h = x @ w1 + b1 (per head), 1-pass fp16 MMA, fp32 accum.
// 512 threads, block tile 128x128, warp grid 4m x 4n (warp tile 32x32).
// smem ~73.7KB -> 2 CTAs/SM. Writes h (fp16) + per-tile stats (from fp32 acc).
// ---------------------------------------------------------------------------
__global__ void __launch_bounds__(512, 2)
k_gemm1(const float *__restrict__ x, const float *__restrict__ b1, int N, int NT)
{
    extern __shared__ unsigned char smraw[];
    __half *Ah = (__half *)smraw;              // 128*LDA
    __half *Bh = Ah + 128 * LDA;               // 128*LDA
    float *psS = (float *)(Bh + 128 * LDA);    // [4][HID]
    float *pqS = psS + 4 * HID;                // [4][HID]

    const int tid = threadIdx.x;
    const int hd = blockIdx.y;
    const int n0 = blockIdx.x * 128;

    // ---- kick off B fill via cp.async (pre-converted, already in layout) ----
    {
        unsigned sBh = (unsigned)__cvta_generic_to_shared(Bh);
        const __half *src = g_w1h + (size_t)hd * 128 * LDA;
        const int NCHK = 128 * LDA / 8;        // 16B chunks
        for (int i = tid; i < NCHK; i += 512)
            cpasync16(sBh + i * 16, src + i * 8);
        cpasync_commit();
    }

    // ---- fill A (x tile), fp16 ----
    #pragma unroll
    for (int i = tid; i < 128 * 32; i += 512) {
        int r = i >> 5, c4 = (i & 31) << 2;
        float4 v = make_float4(0.f, 0.f, 0.f, 0.f);
        int row = n0 + r;
        if (row < N)
            v = *reinterpret_cast<const float4 *>(x + ((size_t)row * H + hd) * FIN + c4);
        st_h4(Ah + r * LDA + c4, __float2half_rn(v.x), __float2half_rn(v.y),
              __float2half_rn(v.z), __float2half_rn(v.w));
    }
    cpasync_wait0();
    __syncthreads();

    const int lane = tid & 31;
    const int w = tid >> 5;
    const int gid = lane >> 2, tig = lane & 3;
    const int wm = w & 3, wn = w >> 2;     // warp tile: rows wm*32.., cols wn*32..

    const int lr = lane & 15;
    const int kh = ((lane >> 4) & 1) << 3;
    unsigned sAh = (unsigned)__cvta_generic_to_shared(Ah);
    unsigned sBh = (unsigned)__cvta_generic_to_shared(Bh);
    unsigned aAd[2], bAd[2];
    #pragma unroll
    for (int mf = 0; mf < 2; mf++)
        aAd[mf] = sAh + ((wm * 32 + mf * 16 + lr) * LDA + kh) * 2;
    #pragma unroll
    for (int g = 0; g < 2; g++)
        bAd[g] = sBh + ((wn * 32 + g * 16 + lr) * LDA + kh) * 2;

    float acc[2][4][4];
    #pragma unroll
    for (int mf = 0; mf < 2; mf++)
        #pragma unroll
        for (int nf = 0; nf < 4; nf++)
            #pragma unroll
            for (int q = 0; q < 4; q++) acc[mf][nf][q] = 0.f;

    #pragma unroll
    for (int kc = 0; kc < 8; kc++) {
        const unsigned kadv = kc * 32;          // 16 elems * 2B
        unsigned ah[2][4];
        #pragma unroll
        for (int mf = 0; mf < 2; mf++)
            ldsm4(ah[mf][0], ah[mf][1], ah[mf][2], ah[mf][3], aAd[mf] + kadv);
        #pragma unroll
        for (int g = 0; g < 2; g++) {
            unsigned bh[4];
            ldsm4(bh[0], bh[1], bh[2], bh[3], bAd[g] + kadv);
            #pragma unroll
            for (int mf = 0; mf < 2; mf++) {
                // cols g*16 + 0..7 -> b-frag {r0, r2}; 8..15 -> {r1, r3}
                mma16816h(acc[mf][g * 2 + 0], ah[mf], bh[0], bh[2]);
                mma16816h(acc[mf][g * 2 + 1], ah[mf], bh[1], bh[3]);
            }
        }
    }

    // ---- epilogue: +b1, store h (fp16), per-column stats from fp32 acc ----
    const float *b1h = b1 + hd * HID;
    #pragma unroll
    for (int nf = 0; nf < 4; nf++) {
        const int col = wn * 32 + nf * 8 + tig * 2;
        const float be = b1h[col], bo = b1h[col + 1];
        float se = 0.f, qe = 0.f, so = 0.f, qo = 0.f;
        #pragma unroll
        for (int mf = 0; mf < 2; mf++) {
            const int r0 = n0 + wm * 32 + mf * 16 + gid;
            const int r1 = r0 + 8;
            float v0 = acc[mf][nf][0] + be;
            float v1 = acc[mf][nf][1] + bo;
            float v2 = acc[mf][nf][2] + be;
            float v3 = acc[mf][nf][3] + bo;
            if (r0 < N) {
                __half2 t = __halves2half2(__float2half_rn(v0), __float2half_rn(v1));
                *reinterpret_cast<__half2 *>(g_h + ((size_t)r0 * H + hd) * HID + col) = t;
                se += v0; qe += v0 * v0; so += v1; qo += v1 * v1;
            }
            if (r1 < N) {
                __half2 t = __halves2half2(__float2half_rn(v2), __float2half_rn(v3));
                *reinterpret_cast<__half2 *>(g_h + ((size_t)r1 * H + hd) * HID + col) = t;
                se += v2; qe += v2 * v2; so += v3; qo += v3 * v3;
            }
        }
        #pragma unroll
        for (int off = 16; off >= 4; off >>= 1) {
            se += __shfl_xor_sync(0xffffffffu, se, off);
            so += __shfl_xor_sync(0xffffffffu, so, off);
            qe += __shfl_xor_sync(0xffffffffu, qe, off);
            qo += __shfl_xor_sync(0xffffffffu, qo, off);
        }
        if (gid == 0) {
            psS[wm * HID + col] = se; psS[wm * HID + col + 1] = so;
            pqS[wm * HID + col] = qe; pqS[wm * HID + col + 1] = qo;
        }
    }
    __syncthreads();
    if (tid < HID) {
        float s = psS[tid] + psS[HID + tid] + psS[2 * HID + tid] + psS[3 * HID + tid];
        float q = pqS[tid] + pqS[HID + tid] + pqS[2 * HID + tid] + pqS[3 * HID + tid];
        size_t o = ((size_t)hd * NT + blockIdx.x) * HID + tid;
        g_psum[o] = s; g_psumsq[o] = q;
    }
}

// ---------------------------------------------------------------------------
// K2a/K2b: deterministic fixed-order reduction of tile stats -> BN scale/shift
// ---------------------------------------------------------------------------
__global__ void k_stats_a(int NT)
{
    const int hd = blockIdx.x, ch = blockIdx.y, c = threadIdx.x;
    const int per = (NT + NCH - 1) / NCH;
    int t0 = ch * per;
    int t1 = min(NT, t0 + per);
    const float *ps = g_psum + (size_t)hd * NT * HID + c;
    const float *pq = g_psumsq + (size_t)hd * NT * HID + c;
    float s0 = 0, s1 = 0, s2 = 0, s3 = 0, q0 = 0, q1 = 0, q2 = 0, q3 = 0;
    int t = t0;
    for (; t + 4 <= t1; t += 4) {
        s0 += ps[(size_t)(t + 0) * HID]; q0 += pq[(size_t)(t + 0) * HID];
        s1 += ps[(size_t)(t + 1) * HID]; q1 += pq[(size_t)(t + 1) * HID];
        s2 += ps[(size_t)(t + 2) * HID]; q2 += pq[(size_t)(t + 2) * HID];
        s3 += ps[(size_t)(t + 3) * HID]; q3 += pq[(size_t)(t + 3) * HID];
    }
    for (; t < t1; t++) { s0 += ps[(size_t)t * HID]; q0 += pq[(size_t)t * HID]; }
    g_ps2[(hd * NCH + ch) * HID + c] = (s0 + s1) + (s2 + s3);
    g_pq2[(hd * NCH + ch) * HID + c] = (q0 + q1) + (q2 + q3);
}

__global__ void k_stats_b(const float *__restrict__ bn_w, const float *__restrict__ bn_b, int N)
{
    const int hd = blockIdx.x, c = threadIdx.x;
    float s = 0.f, q = 0.f;
    #pragma unroll
    for (int ch = 0; ch < NCH; ch++) {
        s += g_ps2[(hd * NCH + ch) * HID + c];
        q += g_pq2[(hd * NCH + ch) * HID + c];
    }
    float invN = 1.0f / (float)N;
    float mean = s * invN;
    float var = fmaxf(q * invN - mean * mean, 0.f);
    float inv = rsqrtf(var + 1e-5f);
    float sc = bn_w[hd * HID + c] * inv;
    g_scale[hd * HID + c] = sc;
    g_shift[hd * HID + c] = bn_b[hd * HID + c] - mean * sc;
}

// ---------------------------------------------------------------------------
// K3: y = relu(h*scale + shift) @ w2 + b2, 1-pass fp16 MMA. h read as fp16.
// 512 threads, block tile 128x64, warp grid 4x4 (warp tile 32x16), 2 CTAs/SM.
// ---------------------------------------------------------------------------
__global__ void __launch_bounds__(512, 2)
k_gemm2(const float *__restrict__ b2, float *__restrict__ out, int N)
{
    extern __shared__ unsigned char smraw[];
    __half *Ah = (__half *)smraw;              // 128*LDA
    __half *Bh = Ah + 128 * LDA;               // 64*LDA
    float *scS = (float *)(Bh + 64 * LDA);
    float *shS = scS + HID;

    const int tid = threadIdx.x;
    const int hd = blockIdx.y;
    const int n0 = blockIdx.x * 128;

    // ---- kick off B fill via cp.async ----
    {
        unsigned sBh = (unsigned)__cvta_generic_to_shared(Bh);
        const __half *src = g_w2h + (size_t)hd * 64 * LDA;
        const int NCHK = 64 * LDA / 8;
        for (int i = tid; i < NCHK; i += 512)
            cpasync16(sBh + i * 16, src + i * 8);
        cpasync_commit();
    }

    if (tid < HID) {
        scS[tid] = g_scale[hd * HID + tid];
        shS[tid] = g_shift[hd * HID + tid];
    }
    __syncthreads();

    // ---- fill A = relu(h*s + t), h loaded as fp16 (uint2 = 4 halves) ----
    #pragma unroll
    for (int i = tid; i < 128 * 32; i += 512) {
        int r = i >> 5, c4 = (i & 31) << 2;
        int row = n0 + r;
        float a0 = 0.f, a1 = 0.f, a2 = 0.f, a3 = 0.f;
        if (row < N) {
            uint2 u = *reinterpret_cast<const uint2 *>(g_h + ((size_t)row * H + hd) * HID + c4);
            __half2 p0 = *reinterpret_cast<__half2 *>(&u.x);
            __half2 p1 = *reinterpret_cast<__half2 *>(&u.y);
            float2 f0 = __half22float2(p0);
            float2 f1 = __half22float2(p1);
            float4 sc = *reinterpret_cast<const float4 *>(scS + c4);
            float4 sh = *reinterpret_cast<const float4 *>(shS + c4);
            a0 = fmaxf(f0.x * sc.x + sh.x, 0.f);
            a1 = fmaxf(f0.y * sc.y + sh.y, 0.f);
            a2 = fmaxf(f1.x * sc.z + sh.z, 0.f);
            a3 = fmaxf(f1.y * sc.w + sh.w, 0.f);
        }
        st_h4(Ah + r * LDA + c4, __float2half_rn(a0), __float2half_rn(a1),
              __float2half_rn(a2), __float2half_rn(a3));
    }
    cpasync_wait0();
    __syncthreads();

    const int lane = tid & 31;
    const int w = tid >> 5;
    const int gid = lane >> 2, tig = lane & 3;
    const int wm = w & 3, wn = w >> 2;     // warp tile: rows wm*32.., cols wn*16..

    const int lr = lane & 15;
    const int kh = ((lane >> 4) & 1) << 3;
    unsigned sAh = (unsigned)__cvta_generic_to_shared(Ah);
    unsigned sBh = (unsigned)__cvta_generic_to_shared(Bh);
    unsigned aAd[2], bAd;
    #pragma unroll
    for (int mf = 0; mf < 2; mf++)
        aAd[mf] = sAh + ((wm * 32 + mf * 16 + lr) * LDA + kh) * 2;
    bAd = sBh + ((wn * 16 + lr) * LDA + kh) * 2;

    float acc[2][2][4];
    #pragma unroll
    for (int mf = 0; mf < 2; mf++)
        #pragma unroll
        for (int nf = 0; nf < 2; nf++)
            #pragma unroll
            for (int q = 0; q < 4; q++) acc[mf][nf][q] = 0.f;

    #pragma unroll
    for (int kc = 0; kc < 8; kc++) {
        const unsigned kadv = kc * 32;
        unsigned ah[2][4], bh[4];
        #pragma unroll
        for (int mf = 0; mf < 2; mf++)
            ldsm4(ah[mf][0], ah[mf][1], ah[mf][2], ah[mf][3], aAd[mf] + kadv);
        ldsm4(bh[0], bh[1], bh[2], bh[3], bAd + kadv);
        #pragma unroll
        for (int mf = 0; mf < 2; mf++) {
            mma16816h(acc[mf][0], ah[mf], bh[0], bh[2]);
            mma16816h(acc[mf][1], ah[mf], bh[1], bh[3]);
        }
    }

    // ---- epilogue: +b2, store y ----
    const float *b2h = b2 + hd * FOUT;
    #pragma unroll
    for (int nf = 0; nf < 2; nf++) {
        const int col = wn * 16 + nf * 8 + tig * 2;
        const float be = b2h[col], bo = b2h[col + 1];
        #pragma unroll
        for (int mf = 0; mf < 2; mf++) {
            const int r0 = n0 + wm * 32 + mf * 16 + gid;
            const int r1 = r0 + 8;
            if (r0 < N) {
                float2 t; t.x = acc[mf][nf][0] + be; t.y = acc[mf][nf][1] + bo;
                *reinterpret_cast<float2 *>(out + ((size_t)r0 * H + hd) * FOUT + col) = t;
            }
            if (r1 < N) {
                float2 t; t.x = acc[mf][nf][2] + be; t.y = acc[mf][nf][3] + bo;
                *reinterpret_cast<float2 *>(out + ((size_t)r1 * H + hd) * FOUT + col) = t;
            }
        }
    }
}

// ---------------------------------------------------------------------------
extern "C" void kernel_launch(void *const *d_in, const int *in_sizes, int n_in,
                              void *d_out, int out_size)
{
    (void)n_in; (void)out_size;
    const float *x    = (const float *)d_in[0];
    const float *w1   = (const float *)d_in[1];
    const float *b1   = (const float *)d_in[2];
    const float *bn_w = (const float *)d_in[3];
    const float *bn_b = (const float *)d_in[4];
    const float *w2   = (const float *)d_in[5];
    const float *b2   = (const float *)d_in[6];
    float *out = (float *)d_out;

    const int N = in_sizes[0] / (H * FIN);
    const int NT = (N + 127) / 128;

    const int SM1 = 2 * 128 * LDA * 2 + 2 * 4 * HID * 4;               // 73728 B
    const int SM3 = (128 * LDA + 64 * LDA) * 2 + 2 * HID * 4;          // 53248 B

    cudaFuncSetAttribute(k_gemm1, cudaFuncAttributeMaxDynamicSharedMemorySize, SM1);
    cudaFuncSetAttribute(k_gemm2, cudaFuncAttributeMaxDynamicSharedMemorySize, SM3);

    k_prep<<<H, 512>>>(w1, w2);
    k_gemm1<<<dim3(NT, H), 512, SM1>>>(x, b1, N, NT);
    k_stats_a<<<dim3(H, NCH), HID>>>(NT);
    k_stats_b<<<H, HID>>>(bn_w, bn_b, N);
    k_gemm2<<<dim3(NT, H), 512, SM3>>>(b2, out, N);
}

// round 17
// speedup vs baseline: 1.1296x; 1.1296x over previous
// GroupMLP round 17 — revert fp16-h (lost twice); r15 structure + gemm2 at
// 3 CTAs/SM (regs fit post-r15) + packed f32x2->f16x2 conversions in fills.
#include <cuda_runtime.h>
#include <cuda_fp16.h>

#define H 8
#define FIN 128
#define HID 128
#define FOUT 64
#define LDA 136          // padded smem stride (elems): 272B rows -> ldmatrix conflict-free
#define NMAX 131072
#define NTMAX (NMAX / 128)
#define NCH 16

// Scratch (static device globals; no runtime allocation)
__device__ float g_h[(size_t)NMAX * H * HID];         // intermediate h [N,H,HID]
__device__ float g_psum[(size_t)H * NTMAX * HID];     // per-tile column sums
__device__ float g_psumsq[(size_t)H * NTMAX * HID];
__device__ float g_ps2[H * NCH * HID];
__device__ float g_pq2[H * NCH * HID];
__device__ float g_scale[H * HID];
__device__ float g_shift[H * HID];

// Pre-converted fp16 weights, already in [n][k]*LDA smem layout
__device__ __half g_w1h[H * 128 * LDA];
__device__ __half g_w2h[H * 64 * LDA];

// 8-byte packed store of 4 fp16 from 4 floats (packed F2FP conversions)
__device__ __forceinline__ void st_h4f(__half *p, float a, float b, float c, float d) {
    float2 f0; f0.x = a; f0.y = b;
    float2 f1; f1.x = c; f1.y = d;
    __half2 t0 = __float22half2_rn(f0);
    __half2 t1 = __float22half2_rn(f1);
    uint2 t;
    t.x = *reinterpret_cast<unsigned *>(&t0);
    t.y = *reinterpret_cast<unsigned *>(&t1);
    *reinterpret_cast<uint2 *>(p) = t;
}

__device__ __forceinline__ void cpasync16(unsigned saddr, const void *gaddr) {
    asm volatile("cp.async.ca.shared.global [%0], [%1], 16;\n" :: "r"(saddr), "l"(gaddr));
}
__device__ __forceinline__ void cpasync_commit() { asm volatile("cp.async.commit_group;\n"); }
__device__ __forceinline__ void cpasync_wait0()  { asm volatile("cp.async.wait_group 0;\n"); }

__device__ __forceinline__ void ldsm4(unsigned &r0, unsigned &r1, unsigned &r2, unsigned &r3,
                                      unsigned addr) {
    asm volatile("ldmatrix.sync.aligned.m8n8.x4.shared.b16 {%0,%1,%2,%3}, [%4];\n"
                 : "=r"(r0), "=r"(r1), "=r"(r2), "=r"(r3) : "r"(addr));
}

__device__ __forceinline__ void mma16816h(float c[4], const unsigned a[4],
                                          unsigned b0, unsigned b1) {
    asm volatile(
        "mma.sync.aligned.m16n8k16.row.col.f32.f16.f16.f32 "
        "{%0,%1,%2,%3}, {%4,%5,%6,%7}, {%8,%9}, {%0,%1,%2,%3};\n"
        : "+f"(c[0]), "+f"(c[1]), "+f"(c[2]), "+f"(c[3])
        : "r"(a[0]), "r"(a[1]), "r"(a[2]), "r"(a[3]), "r"(b0), "r"(b1));
}

// ---------------------------------------------------------------------------
// K0: convert weights to fp16, transposed to [n][k]*LDA layout.
// ---------------------------------------------------------------------------
__global__ void k_prep(const float *__restrict__ w1, const float *__restrict__ w2)
{
    const int hd = blockIdx.x;
    const int tid = threadIdx.x;
    const float *w1h = w1 + (size_t)hd * FIN * HID;
    __half *o1 = g_w1h + (size_t)hd * 128 * LDA;
    for (int i = tid; i < 128 * 128; i += blockDim.x) {
        int n = i & 127, k = i >> 7;
        o1[n * LDA + k] = __float2half_rn(w1h[(size_t)k * HID + n]);
    }
    const float *w2h = w2 + (size_t)hd * HID * FOUT;
    __half *o2 = g_w2h + (size_t)hd * 64 * LDA;
    for (int i = tid; i < 64 * 128; i += blockDim.x) {
        int n = i & 63, k = i >> 6;
        o2[n * LDA + k] = __float2half_rn(w2h[(size_t)k * FOUT + n]);
    }
}

// ---------------------------------------------------------------------------
// K1: h = x @ w1 + b1 (per head), 1-pass fp16 MMA, fp32 accum.
// 512 threads, block tile 128x128, warp grid 4m x 4n (warp tile 32x32).
// smem ~73.7KB -> 2 CTAs/SM. Writes h (fp32) + per-tile stats (from fp32 acc).
// ---------------------------------------------------------------------------
__global__ void __launch_bounds__(512, 2)
k_gemm1(const float *__restrict__ x, const float *__restrict__ b1, int N, int NT)
{
    extern __shared__ unsigned char smraw[];
    __half *Ah = (__half *)smraw;              // 128*LDA
    __half *Bh = Ah + 128 * LDA;               // 128*LDA
    float *psS = (float *)(Bh + 128 * LDA);    // [4][HID]
    float *pqS = psS + 4 * HID;                // [4][HID]

    const int tid = threadIdx.x;
    const int hd = blockIdx.y;
    const int n0 = blockIdx.x * 128;

    // ---- kick off B fill via cp.async (pre-converted, already in layout) ----
    {
        unsigned sBh = (unsigned)__cvta_generic_to_shared(Bh);
        const __half *src = g_w1h + (size_t)hd * 128 * LDA;
        const int NCHK = 128 * LDA / 8;        // 16B chunks
        for (int i = tid; i < NCHK; i += 512)
            cpasync16(sBh + i * 16, src + i * 8);
        cpasync_commit();
    }

    // ---- fill A (x tile), fp16 ----
    #pragma unroll
    for (int i = tid; i < 128 * 32; i += 512) {
        int r = i >> 5, c4 = (i & 31) << 2;
        float4 v = make_float4(0.f, 0.f, 0.f, 0.f);
        int row = n0 + r;
        if (row < N)
            v = *reinterpret_cast<const float4 *>(x + ((size_t)row * H + hd) * FIN + c4);
        st_h4f(Ah + r * LDA + c4, v.x, v.y, v.z, v.w);
    }
    cpasync_wait0();
    __syncthreads();

    const int lane = tid & 31;
    const int w = tid >> 5;
    const int gid = lane >> 2, tig = lane & 3;
    const int wm = w & 3, wn = w >> 2;     // warp tile: rows wm*32.., cols wn*32..

    const int lr = lane & 15;
    const int kh = ((lane >> 4) & 1) << 3;
    unsigned sAh = (unsigned)__cvta_generic_to_shared(Ah);
    unsigned sBh = (unsigned)__cvta_generic_to_shared(Bh);
    unsigned aAd[2], bAd[2];
    #pragma unroll
    for (int mf = 0; mf < 2; mf++)
        aAd[mf] = sAh + ((wm * 32 + mf * 16 + lr) * LDA + kh) * 2;
    #pragma unroll
    for (int g = 0; g < 2; g++)
        bAd[g] = sBh + ((wn * 32 + g * 16 + lr) * LDA + kh) * 2;

    float acc[2][4][4];
    #pragma unroll
    for (int mf = 0; mf < 2; mf++)
        #pragma unroll
        for (int nf = 0; nf < 4; nf++)
            #pragma unroll
            for (int q = 0; q < 4; q++) acc[mf][nf][q] = 0.f;

    #pragma unroll
    for (int kc = 0; kc < 8; kc++) {
        const unsigned kadv = kc * 32;          // 16 elems * 2B
        unsigned ah[2][4];
        #pragma unroll
        for (int mf = 0; mf < 2; mf++)
            ldsm4(ah[mf][0], ah[mf][1], ah[mf][2], ah[mf][3], aAd[mf] + kadv);
        #pragma unroll
        for (int g = 0; g < 2; g++) {
            unsigned bh[4];
            ldsm4(bh[0], bh[1], bh[2], bh[3], bAd[g] + kadv);
            #pragma unroll
            for (int mf = 0; mf < 2; mf++) {
                // cols g*16 + 0..7 -> b-frag {r0, r2}; 8..15 -> {r1, r3}
                mma16816h(acc[mf][g * 2 + 0], ah[mf], bh[0], bh[2]);
                mma16816h(acc[mf][g * 2 + 1], ah[mf], bh[1], bh[3]);
            }
        }
    }

    // ---- epilogue: +b1, store h, per-column stats from fp32 acc ----
    const float *b1h = b1 + hd * HID;
    #pragma unroll
    for (int nf = 0; nf < 4; nf++) {
        const int col = wn * 32 + nf * 8 + tig * 2;
        const float be = b1h[col], bo = b1h[col + 1];
        float se = 0.f, qe = 0.f, so = 0.f, qo = 0.f;
        #pragma unroll
        for (int mf = 0; mf < 2; mf++) {
            const int r0 = n0 + wm * 32 + mf * 16 + gid;
            const int r1 = r0 + 8;
            float v0 = acc[mf][nf][0] + be;
            float v1 = acc[mf][nf][1] + bo;
            float v2 = acc[mf][nf][2] + be;
            float v3 = acc[mf][nf][3] + bo;
            if (r0 < N) {
                float2 t; t.x = v0; t.y = v1;
                *reinterpret_cast<float2 *>(g_h + ((size_t)r0 * H + hd) * HID + col) = t;
                se += v0; qe += v0 * v0; so += v1; qo += v1 * v1;
            }
            if (r1 < N) {
                float2 t; t.x = v2; t.y = v3;
                *reinterpret_cast<float2 *>(g_h + ((size_t)r1 * H + hd) * HID + col) = t;
                se += v2; qe += v2 * v2; so += v3; qo += v3 * v3;
            }
        }
        #pragma unroll
        for (int off = 16; off >= 4; off >>= 1) {
            se += __shfl_xor_sync(0xffffffffu, se, off);
            so += __shfl_xor_sync(0xffffffffu, so, off);
            qe += __shfl_xor_sync(0xffffffffu, qe, off);
            qo += __shfl_xor_sync(0xffffffffu, qo, off);
        }
        if (gid == 0) {
            psS[wm * HID + col] = se; psS[wm * HID + col + 1] = so;
            pqS[wm * HID + col] = qe; pqS[wm * HID + col + 1] = qo;
        }
    }
    __syncthreads();
    if (tid < HID) {
        float s = psS[tid] + psS[HID + tid] + psS[2 * HID + tid] + psS[3 * HID + tid];
        float q = pqS[tid] + pqS[HID + tid] + pqS[2 * HID + tid] + pqS[3 * HID + tid];
        size_t o = ((size_t)hd * NT + blockIdx.x) * HID + tid;
        g_psum[o] = s; g_psumsq[o] = q;
    }
}

// ---------------------------------------------------------------------------
// K2a/K2b: deterministic fixed-order reduction of tile stats -> BN scale/shift
// ---------------------------------------------------------------------------
__global__ void k_stats_a(int NT)
{
    const int hd = blockIdx.x, ch = blockIdx.y, c = threadIdx.x;
    const int per = (NT + NCH - 1) / NCH;
    int t0 = ch * per;
    int t1 = min(NT, t0 + per);
    const float *ps = g_psum + (size_t)hd * NT * HID + c;
    const float *pq = g_psumsq + (size_t)hd * NT * HID + c;
    float s0 = 0, s1 = 0, s2 = 0, s3 = 0, q0 = 0, q1 = 0, q2 = 0, q3 = 0;
    int t = t0;
    for (; t + 4 <= t1; t += 4) {
        s0 += ps[(size_t)(t + 0) * HID]; q0 += pq[(size_t)(t + 0) * HID];
        s1 += ps[(size_t)(t + 1) * HID]; q1 += pq[(size_t)(t + 1) * HID];
        s2 += ps[(size_t)(t + 2) * HID]; q2 += pq[(size_t)(t + 2) * HID];
        s3 += ps[(size_t)(t + 3) * HID]; q3 += pq[(size_t)(t + 3) * HID];
    }
    for (; t < t1; t++) { s0 += ps[(size_t)t * HID]; q0 += pq[(size_t)t * HID]; }
    g_ps2[(hd * NCH + ch) * HID + c] = (s0 + s1) + (s2 + s3);
    g_pq2[(hd * NCH + ch) * HID + c] = (q0 + q1) + (q2 + q3);
}

__global__ void k_stats_b(const float *__restrict__ bn_w, const float *__restrict__ bn_b, int N)
{
    const int hd = blockIdx.x, c = threadIdx.x;
    float s = 0.f, q = 0.f;
    #pragma unroll
    for (int ch = 0; ch < NCH; ch++) {
        s += g_ps2[(hd * NCH + ch) * HID + c];
        q += g_pq2[(hd * NCH + ch) * HID + c];
    }
    float invN = 1.0f / (float)N;
    float mean = s * invN;
    float var = fmaxf(q * invN - mean * mean, 0.f);
    float inv = rsqrtf(var + 1e-5f);
    float sc = bn_w[hd * HID + c] * inv;
    g_scale[hd * HID + c] = sc;
    g_shift[hd * HID + c] = bn_b[hd * HID + c] - mean * sc;
}

// ---------------------------------------------------------------------------
// K3: y = relu(h*scale + shift) @ w2 + b2, 1-pass fp16 MMA.
// 512 threads, block tile 128x64, warp grid 4x4 (warp tile 32x16).
// smem 53.2KB -> 3 CTAs/SM (regs fit post-r15 fragment halving).
// ---------------------------------------------------------------------------
__global__ void __launch_bounds__(512, 3)
k_gemm2(const float *__restrict__ b2, float *__restrict__ out, int N)
{
    extern __shared__ unsigned char smraw[];
    __half *Ah = (__half *)smraw;              // 128*LDA
    __half *Bh = Ah + 128 * LDA;               // 64*LDA
    float *scS = (float *)(Bh + 64 * LDA);
    float *shS = scS + HID;

    const int tid = threadIdx.x;
    const int hd = blockIdx.y;
    const int n0 = blockIdx.x * 128;

    // ---- kick off B fill via cp.async ----
    {
        unsigned sBh = (unsigned)__cvta_generic_to_shared(Bh);
        const __half *src = g_w2h + (size_t)hd * 64 * LDA;
        const int NCHK = 64 * LDA / 8;
        for (int i = tid; i < NCHK; i += 512)
            cpasync16(sBh + i * 16, src + i * 8);
        cpasync_commit();
    }

    if (tid < HID) {
        scS[tid] = g_scale[hd * HID + tid];
        shS[tid] = g_shift[hd * HID + tid];
    }
    __syncthreads();

    // ---- fill A = relu(h*s + t), fp16 ----
    #pragma unroll
    for (int i = tid; i < 128 * 32; i += 512) {
        int r = i >> 5, c4 = (i & 31) << 2;
        int row = n0 + r;
        float4 v = make_float4(0.f, 0.f, 0.f, 0.f);
        if (row < N)
            v = *reinterpret_cast<const float4 *>(g_h + ((size_t)row * H + hd) * HID + c4);
        float4 sc = *reinterpret_cast<const float4 *>(scS + c4);
        float4 sh = *reinterpret_cast<const float4 *>(shS + c4);
        float a0 = fmaxf(v.x * sc.x + sh.x, 0.f);
        float a1 = fmaxf(v.y * sc.y + sh.y, 0.f);
        float a2 = fmaxf(v.z * sc.z + sh.z, 0.f);
        float a3 = fmaxf(v.w * sc.w + sh.w, 0.f);
        if (row >= N) { a0 = a1 = a2 = a3 = 0.f; }
        st_h4f(Ah + r * LDA + c4, a0, a1, a2, a3);
    }
    cpasync_wait0();
    __syncthreads();

    const int lane = tid & 31;
    const int w = tid >> 5;
    const int gid = lane >> 2, tig = lane & 3;
    const int wm = w & 3, wn = w >> 2;     // warp tile: rows wm*32.., cols wn*16..

    const int lr = lane & 15;
    const int kh = ((lane >> 4) & 1) << 3;
    unsigned sAh = (unsigned)__cvta_generic_to_shared(Ah);
    unsigned sBh = (unsigned)__cvta_generic_to_shared(Bh);
    unsigned aAd[2], bAd;
    #pragma unroll
    for (int mf = 0; mf < 2; mf++)
        aAd[mf] = sAh + ((wm * 32 + mf * 16 + lr) * LDA + kh) * 2;
    bAd = sBh + ((wn * 16 + lr) * LDA + kh) * 2;

    float acc[2][2][4];
    #pragma unroll
    for (int mf = 0; mf < 2; mf++)
        #pragma unroll
        for (int nf = 0; nf < 2; nf++)
            #pragma unroll
            for (int q = 0; q < 4; q++) acc[mf][nf][q] = 0.f;

    #pragma unroll
    for (int kc = 0; kc < 8; kc++) {
        const unsigned kadv = kc * 32;
        unsigned ah[2][4], bh[4];
        #pragma unroll
        for (int mf = 0; mf < 2; mf++)
            ldsm4(ah[mf][0], ah[mf][1], ah[mf][2], ah[mf][3], aAd[mf] + kadv);
        ldsm4(bh[0], bh[1], bh[2], bh[3], bAd + kadv);
        #pragma unroll
        for (int mf = 0; mf < 2; mf++) {
            mma16816h(acc[mf][0], ah[mf], bh[0], bh[2]);
            mma16816h(acc[mf][1], ah[mf], bh[1], bh[3]);
        }
    }

    // ---- epilogue: +b2, store y ----
    const float *b2h = b2 + hd * FOUT;
    #pragma unroll
    for (int nf = 0; nf < 2; nf++) {
        const int col = wn * 16 + nf * 8 + tig * 2;
        const float be = b2h[col], bo = b2h[col + 1];
        #pragma unroll
        for (int mf = 0; mf < 2; mf++) {
            const int r0 = n0 + wm * 32 + mf * 16 + gid;
            const int r1 = r0 + 8;
            if (r0 < N) {
                float2 t; t.x = acc[mf][nf][0] + be; t.y = acc[mf][nf][1] + bo;
                *reinterpret_cast<float2 *>(out + ((size_t)r0 * H + hd) * FOUT + col) = t;
            }
            if (r1 < N) {
                float2 t; t.x = acc[mf][nf][2] + be; t.y = acc[mf][nf][3] + bo;
                *reinterpret_cast<float2 *>(out + ((size_t)r1 * H + hd) * FOUT + col) = t;
            }
        }
    }
}

// ---------------------------------------------------------------------------
extern "C" void kernel_launch(void *const *d_in, const int *in_sizes, int n_in,
                              void *d_out, int out_size)
{
    (void)n_in; (void)out_size;
    const float *x    = (const float *)d_in[0];
    const float *w1   = (const float *)d_in[1];
    const float *b1   = (const float *)d_in[2];
    const float *bn_w = (const float *)d_in[3];
    const float *bn_b = (const float *)d_in[4];
    const float *w2   = (const float *)d_in[5];
    const float *b2   = (const float *)d_in[6];
    float *out = (float *)d_out;

    const int N = in_sizes[0] / (H * FIN);
    const int NT = (N + 127) / 128;

    const int SM1 = 2 * 128 * LDA * 2 + 2 * 4 * HID * 4;               // 73728 B
    const int SM3 = (128 * LDA + 64 * LDA) * 2 + 2 * HID * 4;          // 53248 B

    cudaFuncSetAttribute(k_gemm1, cudaFuncAttributeMaxDynamicSharedMemorySize, SM1);
    cudaFuncSetAttribute(k_gemm2, cudaFuncAttributeMaxDynamicSharedMemorySize, SM3);

    k_prep<<<H, 512>>>(w1, w2);
    k_gemm1<<<dim3(NT, H), 512, SM1>>>(x, b1, N, NT);
    k_stats_a<<<dim3(H, NCH), HID>>>(NT);
    k_stats_b<<<H, HID>>>(bn_w, bn_b, N);
    k_gemm2<<<dim3(NT, H), 512, SM3>>>(b2, out, N);
}